// round 10
// baseline (speedup 1.0000x reference)
#include <cuda_runtime.h>
#include <cstdint>

#define MAX_NODES 100000
#define MAX_EDGES 1600000
#define SCAN_BLK 1024

typedef unsigned long long u64;

// Scratch (allocation-free device globals); 256B-aligned for float4 access.
__device__ __align__(256) float g_h[(size_t)MAX_NODES * 128];   // h = X@W (layer1); h2 (64c) reuses
__device__ __align__(256) float g_h2[(size_t)MAX_NODES * 64];   // layer-2 pre-agg features
__device__ __align__(256) float g_dinv[MAX_NODES];
__device__ __align__(256) int   g_degi[MAX_NODES];
__device__ __align__(256) int   g_rtmp[MAX_NODES];
__device__ __align__(256) int   g_row_ptr[MAX_NODES + 1];
__device__ __align__(256) int   g_cursor[MAX_NODES];
__device__ __align__(256) int   g_csr_src[MAX_EDGES];
__device__ __align__(256) int   g_bsums[(MAX_NODES + SCAN_BLK - 1) / SCAN_BLK + 1];
__device__ int g_i64;   // 1 if edge_index is int64, 0 if int32

// ---------------------------------------------------------------------------
// Edge dtype detection (1 warp): int64 values < 1e5 have all-zero high words.
// ---------------------------------------------------------------------------
__global__ void detect_dtype_kernel(const int* __restrict__ ei32, int n_elem) {
    int lim = n_elem < 2048 ? n_elem : 2048;
    int acc = 0;
    for (int i = 1 + 2 * threadIdx.x; i < lim; i += 64) acc |= ei32[i];
    acc = __reduce_or_sync(0xffffffffu, acc);
    if (threadIdx.x == 0) g_i64 = (acc == 0) ? 1 : 0;
}

__device__ __forceinline__ int edge_val(const int* __restrict__ ei32, size_t elem, int sh) {
    return ei32[elem << sh];
}

// ---------------------------------------------------------------------------
// CSR build: degree histogram -> exclusive scan -> cursor fill
// ---------------------------------------------------------------------------
__global__ void count_deg_kernel(const int* __restrict__ ei32, int E, int M) {
    int e = blockIdx.x * blockDim.x + threadIdx.x;
    if (e < E) {
        int sh = g_i64;
        int d = edge_val(ei32, (size_t)E + e, sh);
        if ((unsigned)d < (unsigned)M) atomicAdd(&g_degi[d], 1);
    }
}

__global__ void dinv_kernel(int M) {
    int i = blockIdx.x * blockDim.x + threadIdx.x;
    if (i < M) g_dinv[i] = rsqrtf((float)g_degi[i] + 1.0f);  // +1 self loop
}

__global__ void scan1_kernel(int M) {
    __shared__ int sm[SCAN_BLK];
    int i = blockIdx.x * SCAN_BLK + threadIdx.x;
    int v = (i < M) ? g_degi[i] : 0;
    sm[threadIdx.x] = v;
    __syncthreads();
    for (int off = 1; off < SCAN_BLK; off <<= 1) {
        int t = (threadIdx.x >= off) ? sm[threadIdx.x - off] : 0;
        __syncthreads();
        sm[threadIdx.x] += t;
        __syncthreads();
    }
    if (i < M) g_rtmp[i] = sm[threadIdx.x] - v;          // exclusive within block
    if (threadIdx.x == SCAN_BLK - 1) g_bsums[blockIdx.x] = sm[SCAN_BLK - 1];
}

__global__ void scan2_kernel(int nb) {       // nb <= 128: one-block Hillis-Steele
    __shared__ int sm[128];
    int t = threadIdx.x;
    int v = (t < nb) ? g_bsums[t] : 0;
    sm[t] = v;
    __syncthreads();
    for (int off = 1; off < 128; off <<= 1) {
        int u = (t >= off) ? sm[t - off] : 0;
        __syncthreads();
        sm[t] += u;
        __syncthreads();
    }
    if (t < nb) g_bsums[t] = sm[t] - v;      // exclusive
}

__global__ void scan3_kernel(int M) {
    int i = blockIdx.x * blockDim.x + threadIdx.x;
    if (i < M) {
        int rp = g_rtmp[i] + g_bsums[i / SCAN_BLK];
        g_row_ptr[i] = rp;
        g_cursor[i]  = rp;
        if (i == M - 1) g_row_ptr[M] = rp + g_degi[i];
    }
}

__global__ void fill_csr_kernel(const int* __restrict__ ei32, int E, int M) {
    int e = blockIdx.x * blockDim.x + threadIdx.x;
    if (e < E) {
        int sh = g_i64;
        int s = edge_val(ei32, (size_t)e, sh);
        int d = edge_val(ei32, (size_t)E + e, sh);
        if ((unsigned)s < (unsigned)M && (unsigned)d < (unsigned)M) {
            int pos = atomicAdd(&g_cursor[d], 1);
            g_csr_src[pos] = s;
        }
    }
}

// ---------------------------------------------------------------------------
// fma.rn.f32x2 helper (even/odd-K packed partial sums)
// ---------------------------------------------------------------------------
__device__ __forceinline__ void fma2(u64& d, u64 a, u64 b) {
    asm("fma.rn.f32x2 %0, %1, %2, %0;" : "+l"(d) : "l"(a), "l"(b));
}

// ---------------------------------------------------------------------------
// Layer-1 GEMM: H[M,128] = X[M,128] @ W1[128,128]   (packed f32x2)
// ---------------------------------------------------------------------------
__global__ void __launch_bounds__(256) gemm128_kernel(
        const float* __restrict__ X, const float* __restrict__ W,
        float* __restrict__ H, int M) {
    constexpr int NC = 128, WSTRIDE = 130, ROWS = 64;
    extern __shared__ float sh[];
    float* shWt = sh;                      // NC * WSTRIDE
    float* shX  = sh + NC * WSTRIDE;       // ROWS * 128

    const int tid = threadIdx.x;
    const int rowBase = blockIdx.x * ROWS;

    for (int i = tid; i < 128 * NC; i += 256) {
        int k = i / NC, c = i % NC;
        shWt[c * WSTRIDE + k] = W[i];
    }
    for (int i = tid; i < ROWS * 32; i += 256) {
        int r = i >> 5;
        int gr = rowBase + r;
        float4 v = make_float4(0.f, 0.f, 0.f, 0.f);
        if (gr < M) v = ((const float4*)X)[(size_t)gr * 32 + (i & 31)];
        ((float4*)shX)[i] = v;
    }
    __syncthreads();

    const int warp = tid >> 5, lane = tid & 31;
    const int lc = lane;                   // 32 lanes cover 128 channels (4 groups)
    const int r0 = warp * 8;

    u64 acc[8][4];
    #pragma unroll
    for (int r = 0; r < 8; ++r)
        #pragma unroll
        for (int j = 0; j < 4; ++j) acc[r][j] = 0ULL;

    const float* wbase = &shWt[lc * WSTRIDE];

    #pragma unroll 4
    for (int k2 = 0; k2 < 64; ++k2) {
        u64 w2[4];
        #pragma unroll
        for (int j = 0; j < 4; ++j)
            w2[j] = *(const u64*)&wbase[j * (32 * WSTRIDE) + 2 * k2];
        #pragma unroll
        for (int r = 0; r < 8; ++r) {
            u64 x2 = *(const u64*)&shX[(r0 + r) * 128 + 2 * k2];
            fma2(acc[r][0], x2, w2[0]);
            fma2(acc[r][1], x2, w2[1]);
            fma2(acc[r][2], x2, w2[2]);
            fma2(acc[r][3], x2, w2[3]);
        }
    }

    #pragma unroll
    for (int r = 0; r < 8; ++r) {
        int gr = rowBase + r0 + r;
        if (gr < M) {
            #pragma unroll
            for (int j = 0; j < 4; ++j) {
                u64 a = acc[r][j];
                float lo = __uint_as_float((unsigned)(a & 0xffffffffULL));
                float hi = __uint_as_float((unsigned)(a >> 32));
                H[(size_t)gr * 128 + lc + 32 * j] = lo + hi;
            }
        }
    }
}

// ---------------------------------------------------------------------------
// FUSED layer-1 gather + layer-2 GEMM.
// Block owns 128 dst rows. Phase 1 (warp per row): y-row = relu(dinv*(self +
// sum_s h[s]*dinv[s]) + b1) gathered straight into the GEMM smem X tile.
// Phase 2: H2[128 rows, 64] = Ytile @ W2 with packed f32x2. y never hits GMEM.
// ---------------------------------------------------------------------------
__global__ void __launch_bounds__(256) fused_gather_gemm64_kernel(
        const float* __restrict__ Hs, const float* __restrict__ b1,
        const float* __restrict__ W2, float* __restrict__ H2, int M) {
    constexpr int WSTRIDE = 130, ROWS = 128, NC = 64;
    extern __shared__ float sh[];
    float* shWt = sh;                      // 64 * WSTRIDE
    float* shX  = sh + NC * WSTRIDE;       // 128 * 128 (gathered y tile)

    const int tid = threadIdx.x;
    const int warp = tid >> 5, lane = tid & 31;
    const int rowBase = blockIdx.x * ROWS;

    // Stage W2 transposed.
    for (int i = tid; i < 128 * NC; i += 256) {
        int k = i / NC, c = i % NC;
        shWt[c * WSTRIDE + k] = W2[i];
    }

    // Phase 1: gather 16 rows per warp into shX.
    float4 bv = __ldg((const float4*)&b1[lane * 4]);
    for (int i = 0; i < 16; ++i) {
        int lr = warp * 16 + i;
        int row = rowBase + lr;
        float4 o = make_float4(0.f, 0.f, 0.f, 0.f);
        if (row < M) {
            int p0 = __ldg(&g_row_ptr[row]);
            int p1 = __ldg(&g_row_ptr[row + 1]);
            float di = __ldg(&g_dinv[row]);
            float4 acc = __ldg((const float4*)&Hs[(size_t)row * 128 + lane * 4]);
            acc.x *= di; acc.y *= di; acc.z *= di; acc.w *= di;
            for (int base = p0; base < p1; base += 32) {
                int pl = base + lane;
                int s_l = 0; float dl = 0.f;
                if (pl < p1) { s_l = __ldg(&g_csr_src[pl]); dl = __ldg(&g_dinv[s_l]); }
                int n = min(32, p1 - base);
                int k = 0;
                for (; k + 4 <= n; k += 4) {
                    int s0 = __shfl_sync(0xffffffffu, s_l, k);
                    int s1 = __shfl_sync(0xffffffffu, s_l, k + 1);
                    int s2 = __shfl_sync(0xffffffffu, s_l, k + 2);
                    int s3 = __shfl_sync(0xffffffffu, s_l, k + 3);
                    float d0 = __shfl_sync(0xffffffffu, dl, k);
                    float d1 = __shfl_sync(0xffffffffu, dl, k + 1);
                    float d2 = __shfl_sync(0xffffffffu, dl, k + 2);
                    float d3 = __shfl_sync(0xffffffffu, dl, k + 3);
                    float4 v0 = __ldg((const float4*)&Hs[(size_t)s0 * 128 + lane * 4]);
                    float4 v1 = __ldg((const float4*)&Hs[(size_t)s1 * 128 + lane * 4]);
                    float4 v2 = __ldg((const float4*)&Hs[(size_t)s2 * 128 + lane * 4]);
                    float4 v3 = __ldg((const float4*)&Hs[(size_t)s3 * 128 + lane * 4]);
                    acc.x += v0.x * d0 + v1.x * d1 + v2.x * d2 + v3.x * d3;
                    acc.y += v0.y * d0 + v1.y * d1 + v2.y * d2 + v3.y * d3;
                    acc.z += v0.z * d0 + v1.z * d1 + v2.z * d2 + v3.z * d3;
                    acc.w += v0.w * d0 + v1.w * d1 + v2.w * d2 + v3.w * d3;
                }
                for (; k < n; ++k) {
                    int s = __shfl_sync(0xffffffffu, s_l, k);
                    float d = __shfl_sync(0xffffffffu, dl, k);
                    float4 v = __ldg((const float4*)&Hs[(size_t)s * 128 + lane * 4]);
                    acc.x += v.x * d; acc.y += v.y * d; acc.z += v.z * d; acc.w += v.w * d;
                }
            }
            o.x = fmaxf(acc.x * di + bv.x, 0.f);
            o.y = fmaxf(acc.y * di + bv.y, 0.f);
            o.z = fmaxf(acc.z * di + bv.z, 0.f);
            o.w = fmaxf(acc.w * di + bv.w, 0.f);
        }
        *(float4*)&shX[lr * 128 + lane * 4] = o;
    }
    __syncthreads();

    // Phase 2: GEMM 128x64x128 on the gathered tile.
    const int lc  = lane % 16;
    const int grp = lane / 16;
    const int r0 = warp * 16 + grp * 8;

    u64 acc2[8][4];
    #pragma unroll
    for (int r = 0; r < 8; ++r)
        #pragma unroll
        for (int j = 0; j < 4; ++j) acc2[r][j] = 0ULL;

    const float* wbase = &shWt[lc * WSTRIDE];

    #pragma unroll 4
    for (int k2 = 0; k2 < 64; ++k2) {
        u64 w2v[4];
        #pragma unroll
        for (int j = 0; j < 4; ++j)
            w2v[j] = *(const u64*)&wbase[j * (16 * WSTRIDE) + 2 * k2];
        #pragma unroll
        for (int r = 0; r < 8; ++r) {
            u64 x2 = *(const u64*)&shX[(r0 + r) * 128 + 2 * k2];
            fma2(acc2[r][0], x2, w2v[0]);
            fma2(acc2[r][1], x2, w2v[1]);
            fma2(acc2[r][2], x2, w2v[2]);
            fma2(acc2[r][3], x2, w2v[3]);
        }
    }

    #pragma unroll
    for (int r = 0; r < 8; ++r) {
        int gr = rowBase + r0 + r;
        if (gr < M) {
            #pragma unroll
            for (int j = 0; j < 4; ++j) {
                u64 a = acc2[r][j];
                float lo = __uint_as_float((unsigned)(a & 0xffffffffULL));
                float hi = __uint_as_float((unsigned)(a >> 32));
                H2[(size_t)gr * 64 + lc + 16 * j] = lo + hi;
            }
        }
    }
}

// ---------------------------------------------------------------------------
// Layer-2 gather: out[d] = dinv[d]*(h2[d]*dinv[d] + sum_s h2[s]*dinv[s]) + b2
// ---------------------------------------------------------------------------
__global__ void gather64_kernel(const float* __restrict__ Hs, const float* __restrict__ b,
                                float* __restrict__ out, int M) {
    int row = (blockIdx.x * blockDim.x + threadIdx.x) >> 5;
    int lane = threadIdx.x & 31;
    if (row >= M) return;
    int p0 = __ldg(&g_row_ptr[row]);
    int p1 = __ldg(&g_row_ptr[row + 1]);
    float di = __ldg(&g_dinv[row]);
    float2 acc = __ldg((const float2*)&Hs[(size_t)row * 64 + lane * 2]);    // self loop
    acc.x *= di; acc.y *= di;
    for (int base = p0; base < p1; base += 32) {
        int pl = base + lane;
        int s_l = 0; float dl = 0.f;
        if (pl < p1) { s_l = __ldg(&g_csr_src[pl]); dl = __ldg(&g_dinv[s_l]); }
        int n = min(32, p1 - base);
        int k = 0;
        for (; k + 4 <= n; k += 4) {
            int s0 = __shfl_sync(0xffffffffu, s_l, k);
            int s1 = __shfl_sync(0xffffffffu, s_l, k + 1);
            int s2 = __shfl_sync(0xffffffffu, s_l, k + 2);
            int s3 = __shfl_sync(0xffffffffu, s_l, k + 3);
            float d0 = __shfl_sync(0xffffffffu, dl, k);
            float d1 = __shfl_sync(0xffffffffu, dl, k + 1);
            float d2 = __shfl_sync(0xffffffffu, dl, k + 2);
            float d3 = __shfl_sync(0xffffffffu, dl, k + 3);
            float2 v0 = __ldg((const float2*)&Hs[(size_t)s0 * 64 + lane * 2]);
            float2 v1 = __ldg((const float2*)&Hs[(size_t)s1 * 64 + lane * 2]);
            float2 v2 = __ldg((const float2*)&Hs[(size_t)s2 * 64 + lane * 2]);
            float2 v3 = __ldg((const float2*)&Hs[(size_t)s3 * 64 + lane * 2]);
            acc.x += v0.x * d0 + v1.x * d1 + v2.x * d2 + v3.x * d3;
            acc.y += v0.y * d0 + v1.y * d1 + v2.y * d2 + v3.y * d3;
        }
        for (; k < n; ++k) {
            int s = __shfl_sync(0xffffffffu, s_l, k);
            float d = __shfl_sync(0xffffffffu, dl, k);
            float2 v = __ldg((const float2*)&Hs[(size_t)s * 64 + lane * 2]);
            acc.x += v.x * d; acc.y += v.y * d;
        }
    }
    float2 bv = __ldg((const float2*)&b[lane * 2]);
    float2 o;
    o.x = acc.x * di + bv.x;
    o.y = acc.y * di + bv.y;
    *(float2*)&out[(size_t)row * 64 + lane * 2] = o;
}

// ---------------------------------------------------------------------------
// Launch
// ---------------------------------------------------------------------------
extern "C" void kernel_launch(void* const* d_in, const int* in_sizes, int n_in,
                              void* d_out, int out_size) {
    int idxs[8];
    for (int i = 0; i < n_in; ++i) idxs[i] = i;
    for (int i = 0; i < n_in; ++i)
        for (int j = i + 1; j < n_in; ++j)
            if (in_sizes[idxs[j]] > in_sizes[idxs[i]]) { int t = idxs[i]; idxs[i] = idxs[j]; idxs[j] = t; }

    const float* x    = (const float*)d_in[idxs[0]];
    const int*   ei32 = (const int*)  d_in[idxs[1]];
    const float* W1   = (const float*)d_in[idxs[2]];
    const float* W2   = (const float*)d_in[idxs[3]];
    const float* b1   = (const float*)d_in[idxs[4]];
    const float* b2   = (const float*)d_in[idxs[5]];
    const int x_elems = in_sizes[idxs[0]];
    const int e_elems = in_sizes[idxs[1]];

    const int M = x_elems / 128;   // 100000
    const int E = e_elems / 2;     // 1600000
    const int NB = (M + SCAN_BLK - 1) / SCAN_BLK;

    void *p_degi, *p_h, *p_h2;
    cudaGetSymbolAddress(&p_degi, g_degi);
    cudaGetSymbolAddress(&p_h,    g_h);
    cudaGetSymbolAddress(&p_h2,   g_h2);

    const int SMEM128 = (128 * 130 + 64 * 128) * 4;   // 99,328 B
    const int SMEMF   = (64 * 130 + 128 * 128) * 4;   // 98,816 B
    cudaFuncSetAttribute(gemm128_kernel, cudaFuncAttributeMaxDynamicSharedMemorySize, SMEM128);
    cudaFuncSetAttribute(fused_gather_gemm64_kernel, cudaFuncAttributeMaxDynamicSharedMemorySize, SMEMF);

    static cudaStream_t sB = nullptr;
    static cudaEvent_t evF = nullptr, evJ = nullptr;
    if (!sB) {
        cudaStreamCreateWithFlags(&sB, cudaStreamNonBlocking);
        cudaEventCreateWithFlags(&evF, cudaEventDisableTiming);
        cudaEventCreateWithFlags(&evJ, cudaEventDisableTiming);
    }

    // Fork: CSR chain on side stream sB (overlaps gemm128).
    cudaEventRecord(evF, 0);
    cudaStreamWaitEvent(sB, evF, 0);
    detect_dtype_kernel<<<1, 32, 0, sB>>>(ei32, e_elems);
    cudaMemsetAsync(p_degi, 0, (size_t)M * sizeof(int), sB);
    count_deg_kernel<<<(E + 255) / 256, 256, 0, sB>>>(ei32, E, M);
    dinv_kernel<<<(M + 255) / 256, 256, 0, sB>>>(M);
    scan1_kernel<<<NB, SCAN_BLK, 0, sB>>>(M);
    scan2_kernel<<<1, 128, 0, sB>>>(NB);
    scan3_kernel<<<(M + 255) / 256, 256, 0, sB>>>(M);
    fill_csr_kernel<<<(E + 255) / 256, 256, 0, sB>>>(ei32, E, M);
    cudaEventRecord(evJ, sB);

    // Concurrent: layer-1 GEMM (depends only on x, W1).
    gemm128_kernel<<<(M + 63) / 64, 256, SMEM128>>>(x, W1, (float*)p_h, M);

    // Join, then fused gather+gemm64, then final gather.
    cudaStreamWaitEvent(0, evJ, 0);
    fused_gather_gemm64_kernel<<<(M + 127) / 128, 256, SMEMF>>>(
        (const float*)p_h, b1, W2, (float*)p_h2, M);
    gather64_kernel<<<(M * 32 + 255) / 256, 256>>>(
        (const float*)p_h2, b2, (float*)d_out, M);
}